// round 2
// baseline (speedup 1.0000x reference)
#include <cuda_runtime.h>

// Problem constants
#define IN_CH 16
#define OUT_CH 32
#define KSZ 3
#define NUM_POINTS 3
#define NUM_INPUTS (IN_CH * KSZ * KSZ)   // 144
#define BATCH 8
#define H 32
#define W 32
#define N_PAIRS (NUM_INPUTS * OUT_CH)    // 4608

// Per-(i,o) piecewise coefficients, o-contiguous ([i][o])
__device__ float g_p1[N_PAIRS];
__device__ float g_s0[N_PAIRS];
__device__ float g_s1[N_PAIRS];
__device__ float g_base[OUT_CH];

// ---------------------------------------------------------------------------
// Kernel 1: turn (positions, values) into slope/threshold form.
//   y(x) = v1 + s*(x - p1),  s = (x>=p1 ? s1 : s0)
//   base[o] = sum_i v1[i][o]   (input-independent part of the sum)
// ---------------------------------------------------------------------------
__global__ void apc_coef_kernel(const float* __restrict__ pos,
                                const float* __restrict__ val) {
    int t = blockIdx.x * blockDim.x + threadIdx.x;
    if (t < N_PAIRS) {
        const float* p = pos + t * 3;
        const float* v = val + t * 3;
        float p0 = p[0], p1 = p[1], p2 = p[2];
        float v0 = v[0], v1 = v[1], v2 = v[2];
        g_p1[t] = p1;
        g_s0[t] = (v1 - v0) / (p1 - p0);
        g_s1[t] = (v2 - v1) / (p2 - p1);
    }
    if (blockIdx.x == 0 && threadIdx.x < OUT_CH) {
        float s = 0.f;
        #pragma unroll 16
        for (int i = 0; i < NUM_INPUTS; i++)
            s += val[(i * OUT_CH + threadIdx.x) * 3 + 1];
        g_base[threadIdx.x] = s;
    }
}

// ---------------------------------------------------------------------------
// Kernel 2: main compute.
//   Block = (image b, output row y). 256 threads = 8 warps.
//   lane = output channel o; warp w owns input channels {2w, 2w+1} (18 i's).
//   Coefficients for the warp's 18 i's live in registers.
//   Input tile (16ch x 3rows x 34cols, zero halo) staged in smem; the per-i
//   x value is a warp-uniform broadcast LDS with a compile-time immediate.
//   Cross-warp reduction through padded smem partials (conflict-free).
// ---------------------------------------------------------------------------
#define TILE_ROW 34
#define TILE_CH  (3 * TILE_ROW)          // 102 floats per channel
#define TILE_ELEMS (IN_CH * TILE_CH)     // 1632

__global__ __launch_bounds__(256, 2)
void apc_main_kernel(const float* __restrict__ x, float* __restrict__ out) {
    __shared__ float tile[TILE_ELEMS];                 // 6528 B
    __shared__ float partial[8][32][33];               // 33792 B, padded

    const int tid = threadIdx.x;
    const int b = blockIdx.x >> 5;       // image
    const int y = blockIdx.x & 31;       // output row

    // ---- stage input rows y-1..y+1 with zero halo ----
    const float* xb = x + b * (IN_CH * H * W);
    for (int idx = tid; idx < TILE_ELEMS; idx += 256) {
        int c   = idx / TILE_CH;
        int rem = idx - c * TILE_CH;
        int r   = rem / TILE_ROW;
        int col = rem - r * TILE_ROW;
        int gy = y + r - 1;
        int gx = col - 1;
        float v = 0.f;
        if ((unsigned)gy < (unsigned)H && (unsigned)gx < (unsigned)W)
            v = xb[(c * H + gy) * W + gx];
        tile[idx] = v;
    }

    // ---- load this thread's 18 coefficient triples into registers ----
    const int w = tid >> 5;      // warp id: input-channel pair
    const int o = tid & 31;      // lane id: output channel
    float cp1[18], cs0[18], cs1[18];
    {
        const int i0 = w * 18;
        #pragma unroll
        for (int j = 0; j < 18; j++) {
            int idx = (i0 + j) * OUT_CH + o;   // o-contiguous: coalesced
            cp1[j] = g_p1[idx];
            cs0[j] = g_s0[idx];
            cs1[j] = g_s1[idx];
        }
    }
    __syncthreads();

    // ---- main loop: 32 pixels x 18 i's, 32 o's per warp ----
    const float* tb = tile + w * 2 * TILE_CH;   // this warp's 2 channels
    for (int px = 0; px < 32; px++) {
        float acc0 = 0.f, acc1 = 0.f;
        #pragma unroll
        for (int j = 0; j < 18; j++) {
            const int c  = j / 9;
            const int kh = (j % 9) / 3;
            const int kw = j % 3;
            // warp-uniform broadcast; compile-time immediate offset
            float xv = tb[c * TILE_CH + kh * TILE_ROW + kw + px];
            float d  = xv - cp1[j];
            float s  = (d >= 0.f) ? cs1[j] : cs0[j];
            if (j & 1) acc1 = fmaf(s, d, acc1);
            else       acc0 = fmaf(s, d, acc0);
        }
        partial[w][px][o] = acc0 + acc1;       // lanes contiguous: no conflict
    }
    __syncthreads();

    // ---- reduce 8 warp-partials per (px, o) and write out ----
    // thread tid handles (o = tid/32 + 8j, px = tid%32), j = 0..3
    float* ob = out + b * (OUT_CH * H * W) + y * W;
    for (int q = tid; q < 32 * OUT_CH; q += 256) {
        int oo = q >> 5;
        int px = q & 31;
        float s = g_base[oo];
        #pragma unroll
        for (int ww = 0; ww < 8; ww++)
            s += partial[ww][px][oo];          // stride-33: conflict-free
        ob[oo * (H * W) + px] = s;             // px contiguous: coalesced
    }
}

extern "C" void kernel_launch(void* const* d_in, const int* in_sizes, int n_in,
                              void* d_out, int out_size) {
    const float* x   = (const float*)d_in[0];
    const float* pos = (const float*)d_in[1];
    const float* val = (const float*)d_in[2];
    float* out = (float*)d_out;

    apc_coef_kernel<<<(N_PAIRS + 255) / 256, 256>>>(pos, val);
    apc_main_kernel<<<BATCH * H, 256>>>(x, out);
}